// round 10
// baseline (speedup 1.0000x reference)
#include <cuda_runtime.h>
#include <cstdint>

#define D    64
#define BM   128
#define BN   128
#define PAD  68          // words; 68 mod 32 == 4 -> conflict-free fragment LDS

// ---------------------------------------------------------------------------
__device__ __forceinline__ uint32_t f2tf32(float f) {
    uint32_t u;
    asm("cvt.rna.tf32.f32 %0, %1;" : "=r"(u) : "f"(f));
    return u;
}

// ---------------------------------------------------------------------------
// 128x128 tile per CTA, 4 warps (2x2), warp tile 64x64, 2 CTAs/SM.
// - cross term: mma.sync m16n8k8 tf32 (validated core).
// - row/col norms accumulated on fragment registers inside the K loop
//   (k coverage: each q-lane sees k === q (mod 4); shfl-xor over q completes).
// - epilogue: per-warp smem transpose with XOR(g<<2) swizzle -> STG.128,
//   4 full 128B lines per store instruction.
// ---------------------------------------------------------------------------
__global__ __launch_bounds__(128, 2)
void dist_kernel(const float* __restrict__ x1, const float* __restrict__ x2,
                 float* __restrict__ out, int M) {
    extern __shared__ uint32_t smem[];
    uint32_t* sa = smem;                      // [BM][PAD] tf32 bits
    uint32_t* sb = smem + BM * PAD;           // [BN][PAD]
    float* snrm_b = (float*)(smem + 2 * BM * PAD);  // [128] B col norms

    const int n0  = blockIdx.y * BM;
    const int m0  = blockIdx.x * BN;
    const int tid = threadIdx.x;
    const int wid = tid >> 5;
    const int lane = tid & 31;
    const int wm = wid >> 1;          // 0..1 : 64-row band
    const int wn = wid & 1;           // 0..1 : 64-col band
    const int g  = lane >> 2;         // 0..7
    const int q  = lane & 3;          // 0..3

    // ---- stage tiles: gmem float4 -> tf32(RNA) -> smem (A+B fused for MLP) ----
#pragma unroll
    for (int p = 0; p < 16; ++p) {
        int idx = tid + p * 128;
        int r = idx >> 4, c4 = (idx & 15) * 4;
        float4 va = *(const float4*)(x1 + (size_t)(n0 + r) * D + c4);
        float4 vb = *(const float4*)(x2 + (size_t)(m0 + r) * D + c4);
        *(uint4*)(sa + r * PAD + c4) =
            make_uint4(f2tf32(va.x), f2tf32(va.y), f2tf32(va.z), f2tf32(va.w));
        *(uint4*)(sb + r * PAD + c4) =
            make_uint4(f2tf32(vb.x), f2tf32(vb.y), f2tf32(vb.z), f2tf32(vb.w));
    }
    __syncthreads();

    float acc[4][8][4];
#pragma unroll
    for (int i = 0; i < 4; ++i)
#pragma unroll
        for (int j = 0; j < 8; ++j)
#pragma unroll
            for (int c = 0; c < 4; ++c) acc[i][j][c] = 0.f;

    float nA0[4] = {0.f, 0.f, 0.f, 0.f};   // rows wm*64 + mf*16 + g
    float nA1[4] = {0.f, 0.f, 0.f, 0.f};   // rows wm*64 + mf*16 + g + 8
    float nB[8]  = {0.f, 0.f, 0.f, 0.f, 0.f, 0.f, 0.f, 0.f};  // cols wn*64+nf*8+g

    // ---- K loop: 8 steps of k=8, norms folded onto fragment registers ----
#pragma unroll
    for (int ks = 0; ks < 8; ++ks) {
        const int kb = ks * 8;

        uint32_t bfr[8][2];
#pragma unroll
        for (int nf = 0; nf < 8; ++nf) {
            const uint32_t* bp = sb + (wn * 64 + nf * 8 + g) * PAD + kb + q;
            bfr[nf][0] = bp[0];
            bfr[nf][1] = bp[4];
            float b0 = __uint_as_float(bfr[nf][0]);
            float b1 = __uint_as_float(bfr[nf][1]);
            nB[nf] = fmaf(b0, b0, nB[nf]);
            nB[nf] = fmaf(b1, b1, nB[nf]);
        }

#pragma unroll
        for (int mf = 0; mf < 4; ++mf) {
            const int r = wm * 64 + mf * 16 + g;
            const uint32_t* ap = sa + r * PAD + kb + q;
            uint32_t a0 = ap[0];
            uint32_t a1 = ap[8 * PAD];
            uint32_t a2 = ap[4];
            uint32_t a3 = ap[8 * PAD + 4];
            float f0 = __uint_as_float(a0), f1 = __uint_as_float(a1);
            float f2 = __uint_as_float(a2), f3 = __uint_as_float(a3);
            nA0[mf] = fmaf(f0, f0, nA0[mf]); nA0[mf] = fmaf(f2, f2, nA0[mf]);
            nA1[mf] = fmaf(f1, f1, nA1[mf]); nA1[mf] = fmaf(f3, f3, nA1[mf]);
#pragma unroll
            for (int nf = 0; nf < 8; ++nf) {
                asm volatile(
                    "mma.sync.aligned.m16n8k8.row.col.f32.tf32.tf32.f32 "
                    "{%0,%1,%2,%3}, {%4,%5,%6,%7}, {%8,%9}, {%0,%1,%2,%3};"
                    : "+f"(acc[mf][nf][0]), "+f"(acc[mf][nf][1]),
                      "+f"(acc[mf][nf][2]), "+f"(acc[mf][nf][3])
                    : "r"(a0), "r"(a1), "r"(a2), "r"(a3),
                      "r"(bfr[nf][0]), "r"(bfr[nf][1]));
            }
        }
    }

    // ---- complete norms: reduce over the 4 q-lanes (xor 1, xor 2) ----
#pragma unroll
    for (int mf = 0; mf < 4; ++mf) {
        nA0[mf] += __shfl_xor_sync(0xFFFFFFFF, nA0[mf], 1);
        nA0[mf] += __shfl_xor_sync(0xFFFFFFFF, nA0[mf], 2);
        nA1[mf] += __shfl_xor_sync(0xFFFFFFFF, nA1[mf], 1);
        nA1[mf] += __shfl_xor_sync(0xFFFFFFFF, nA1[mf], 2);
    }
#pragma unroll
    for (int nf = 0; nf < 8; ++nf) {
        nB[nf] += __shfl_xor_sync(0xFFFFFFFF, nB[nf], 1);
        nB[nf] += __shfl_xor_sync(0xFFFFFFFF, nB[nf], 2);
    }
    if (q == 0) {
#pragma unroll
        for (int nf = 0; nf < 8; ++nf)
            snrm_b[wn * 64 + nf * 8 + g] = nB[nf];
    }
    __syncthreads();   // all fragment reads done; sa/sb become epilogue buffers

    // ---- epilogue phase 1: d2 into per-warp swizzled smem buffer ----
    float* buf = (float*)smem + wid * 4096;   // 64x64 floats, XOR(g<<2) swizzle

    float2 s2v[8];
#pragma unroll
    for (int nf = 0; nf < 8; ++nf)
        s2v[nf] = *(const float2*)&snrm_b[wn * 64 + nf * 8 + 2 * q];

#pragma unroll
    for (int mf = 0; mf < 4; ++mf) {
        const float s1a = nA0[mf];
        const float s1b = nA1[mf];
        const int r0 = mf * 16 + g;
#pragma unroll
        for (int nf = 0; nf < 8; ++nf) {
            const int c = nf * 8 + 2 * q;
            float2 ra, rb;
            ra.x = fmaxf(fmaf(-2.f, acc[mf][nf][0], s1a + s2v[nf].x), 0.f);
            ra.y = fmaxf(fmaf(-2.f, acc[mf][nf][1], s1a + s2v[nf].y), 0.f);
            rb.x = fmaxf(fmaf(-2.f, acc[mf][nf][2], s1b + s2v[nf].x), 0.f);
            rb.y = fmaxf(fmaf(-2.f, acc[mf][nf][3], s1b + s2v[nf].y), 0.f);
            *(float2*)(buf + ((r0 * 64 + c) ^ (g << 2)))       = ra;
            *(float2*)(buf + (((r0 + 8) * 64 + c) ^ (g << 2))) = rb;
        }
    }
    __syncwarp();

    // ---- epilogue phase 2: row-major readback -> STG.128 (4 lines/instr) ----
    {
        const int rhalf = lane >> 4;           // 0..1
        const int j     = lane & 15;           // quad index within row
#pragma unroll
        for (int t = 0; t < 32; ++t) {
            const int rl = 2 * t + rhalf;      // local row 0..63
            const int w  = rl * 64 + 4 * j;
            const float4 v = *(const float4*)(buf + (w ^ ((rl & 7) << 2)));
            __stcs((float4*)(out + (size_t)(n0 + wm * 64 + rl) * M
                                  + m0 + wn * 64 + 4 * j), v);
        }
    }
}

// ---------------------------------------------------------------------------
extern "C" void kernel_launch(void* const* d_in, const int* in_sizes, int n_in,
                              void* d_out, int out_size) {
    const float* x1 = (const float*)d_in[0];
    const float* x2 = (const float*)d_in[1];
    float* out = (float*)d_out;

    const int N = in_sizes[0] / D;   // 8192
    const int M = in_sizes[1] / D;   // 8192

    const int smem_bytes = 2 * BM * PAD * sizeof(uint32_t) + 128 * sizeof(float);
    cudaFuncSetAttribute(dist_kernel,
                         cudaFuncAttributeMaxDynamicSharedMemorySize, smem_bytes);

    dim3 grid(M / BN, N / BM);
    dist_kernel<<<grid, 128, smem_bytes>>>(x1, x2, out, M);
}

// round 11
// speedup vs baseline: 1.0309x; 1.0309x over previous
#include <cuda_runtime.h>
#include <cstdint>

#define D    64
#define BM   128
#define BN   128
#define PAD  68          // words; 68 mod 32 == 4 -> conflict-free fragment LDS
#define NROWS 8192

__device__ float g_sq1[NROWS];
__device__ float g_sq2[NROWS];

// ---------------------------------------------------------------------------
__device__ __forceinline__ uint32_t f2tf32(float f) {
    uint32_t u;
    asm("cvt.rna.tf32.f32 %0, %1;" : "=r"(u) : "f"(f));
    return u;
}
__device__ __forceinline__ float tf32val(float f) {
    return __uint_as_float(f2tf32(f));
}

// ---------------------------------------------------------------------------
// Row norms of BOTH inputs in one launch, from tf32-rounded values
// (self-consistent with the MMA operands).
// ---------------------------------------------------------------------------
__global__ void norm_kernel(const float* __restrict__ x1,
                            const float* __restrict__ x2) {
    int r = blockIdx.x * blockDim.x + threadIdx.x;
    const float* x = (r < NROWS) ? x1 : x2;
    int row = r & (NROWS - 1);
    const float4* p = (const float4*)(x + (size_t)row * D);
    float s = 0.f;
#pragma unroll
    for (int i = 0; i < D / 4; ++i) {
        float4 v = p[i];
        float a = tf32val(v.x), b = tf32val(v.y);
        float c = tf32val(v.z), d = tf32val(v.w);
        s = fmaf(a, a, s); s = fmaf(b, b, s);
        s = fmaf(c, c, s); s = fmaf(d, d, s);
    }
    if (r < NROWS) g_sq1[row] = s; else g_sq2[row] = s;
}

// ---------------------------------------------------------------------------
// 128x128 tile per CTA, 4 warps (2x2), warp tile 64x64, 2 CTAs/SM.
// K loop identical to the validated R8 core. Norms precomputed.
// Epilogue: per-warp smem transpose, swizzle col ^ 8*(row&3)
// (conflict-free per half-warp STS.64 / quarter-warp LDS.128), then STG.128.
// ---------------------------------------------------------------------------
__global__ __launch_bounds__(128, 2)
void dist_kernel(const float* __restrict__ x1, const float* __restrict__ x2,
                 float* __restrict__ out, int M) {
    extern __shared__ uint32_t smem[];
    uint32_t* sa = smem;                      // [BM][PAD] tf32 bits
    uint32_t* sb = smem + BM * PAD;           // [BN][PAD]
    float* snA = (float*)(smem + 2 * BM * PAD);        // [128] A row norms
    float* snB = snA + BM;                              // [128] B row norms

    const int n0  = blockIdx.y * BM;
    const int m0  = blockIdx.x * BN;
    const int tid = threadIdx.x;
    const int wid = tid >> 5;
    const int lane = tid & 31;
    const int wm = wid >> 1;          // 0..1 : 64-row band
    const int wn = wid & 1;           // 0..1 : 64-col band
    const int g  = lane >> 2;         // 0..7
    const int q  = lane & 3;          // 0..3

    // ---- stage tiles: gmem float4 -> tf32(RNA) -> smem; norms -> smem ----
#pragma unroll
    for (int p = 0; p < 16; ++p) {
        int idx = tid + p * 128;
        int r = idx >> 4, c4 = (idx & 15) * 4;
        float4 va = *(const float4*)(x1 + (size_t)(n0 + r) * D + c4);
        float4 vb = *(const float4*)(x2 + (size_t)(m0 + r) * D + c4);
        *(uint4*)(sa + r * PAD + c4) =
            make_uint4(f2tf32(va.x), f2tf32(va.y), f2tf32(va.z), f2tf32(va.w));
        *(uint4*)(sb + r * PAD + c4) =
            make_uint4(f2tf32(vb.x), f2tf32(vb.y), f2tf32(vb.z), f2tf32(vb.w));
    }
    snA[tid] = g_sq1[n0 + tid];
    snB[tid] = g_sq2[m0 + tid];
    __syncthreads();

    float acc[4][8][4];
#pragma unroll
    for (int i = 0; i < 4; ++i)
#pragma unroll
        for (int j = 0; j < 8; ++j)
#pragma unroll
            for (int c = 0; c < 4; ++c) acc[i][j][c] = 0.f;

    // ---- K loop: 8 steps of k=8 (validated core) ----
#pragma unroll
    for (int ks = 0; ks < 8; ++ks) {
        const int kb = ks * 8;
        uint32_t bfr[8][2];
#pragma unroll
        for (int nf = 0; nf < 8; ++nf) {
            const uint32_t* bp = sb + (wn * 64 + nf * 8 + g) * PAD + kb + q;
            bfr[nf][0] = bp[0];
            bfr[nf][1] = bp[4];
        }
#pragma unroll
        for (int mf = 0; mf < 4; ++mf) {
            const int r = wm * 64 + mf * 16 + g;
            const uint32_t* ap = sa + r * PAD + kb + q;
            uint32_t a0 = ap[0];
            uint32_t a1 = ap[8 * PAD];
            uint32_t a2 = ap[4];
            uint32_t a3 = ap[8 * PAD + 4];
#pragma unroll
            for (int nf = 0; nf < 8; ++nf) {
                asm volatile(
                    "mma.sync.aligned.m16n8k8.row.col.f32.tf32.tf32.f32 "
                    "{%0,%1,%2,%3}, {%4,%5,%6,%7}, {%8,%9}, {%0,%1,%2,%3};"
                    : "+f"(acc[mf][nf][0]), "+f"(acc[mf][nf][1]),
                      "+f"(acc[mf][nf][2]), "+f"(acc[mf][nf][3])
                    : "r"(a0), "r"(a1), "r"(a2), "r"(a3),
                      "r"(bfr[nf][0]), "r"(bfr[nf][1]));
            }
        }
    }

    // ---- epilogue norms from smem (read BEFORE smem is reused) ----
    float s1lo[4], s1hi[4];
#pragma unroll
    for (int mf = 0; mf < 4; ++mf) {
        s1lo[mf] = snA[wm * 64 + mf * 16 + g];
        s1hi[mf] = snA[wm * 64 + mf * 16 + g + 8];
    }
    float2 s2v[8];
#pragma unroll
    for (int nf = 0; nf < 8; ++nf)
        s2v[nf] = *(const float2*)&snB[wn * 64 + nf * 8 + 2 * q];

    __syncthreads();   // fragment reads + norm reads done; sa/sb reusable

    // ---- phase 1: d2 into per-warp swizzled 64x64 buffer ----
    float* buf = (float*)smem + wid * 4096;
    const int sw = 8 * (g & 3);          // row-dependent col swizzle (row&3 == g&3)
#pragma unroll
    for (int mf = 0; mf < 4; ++mf) {
        const int r0 = mf * 16 + g;
#pragma unroll
        for (int nf = 0; nf < 8; ++nf) {
            const int c = nf * 8 + 2 * q;
            float2 ra, rb;
            ra.x = fmaxf(fmaf(-2.f, acc[mf][nf][0], s1lo[mf] + s2v[nf].x), 0.f);
            ra.y = fmaxf(fmaf(-2.f, acc[mf][nf][1], s1lo[mf] + s2v[nf].y), 0.f);
            rb.x = fmaxf(fmaf(-2.f, acc[mf][nf][2], s1hi[mf] + s2v[nf].x), 0.f);
            rb.y = fmaxf(fmaf(-2.f, acc[mf][nf][3], s1hi[mf] + s2v[nf].y), 0.f);
            *(float2*)(buf + r0 * 64 + (c ^ sw))       = ra;   // (r0+8)&3 == r0&3
            *(float2*)(buf + (r0 + 8) * 64 + (c ^ sw)) = rb;
        }
    }
    __syncwarp();

    // ---- phase 2: de-swizzled row-major readback -> STG.128 ----
    {
        const int rh = lane >> 4;            // 0..1 : row within pair
        const int j  = lane & 15;            // float4 index within 64-col row
#pragma unroll
        for (int t = 0; t < 32; ++t) {
            const int rl = 2 * t + rh;       // local row 0..63
            const float4 v = *(const float4*)(buf + rl * 64
                                              + ((4 * j) ^ (8 * (rl & 3))));
            __stcs((float4*)(out + (size_t)(n0 + wm * 64 + rl) * M
                                  + m0 + wn * 64 + 4 * j), v);
        }
    }
}

// ---------------------------------------------------------------------------
extern "C" void kernel_launch(void* const* d_in, const int* in_sizes, int n_in,
                              void* d_out, int out_size) {
    const float* x1 = (const float*)d_in[0];
    const float* x2 = (const float*)d_in[1];
    float* out = (float*)d_out;

    const int N = in_sizes[0] / D;   // 8192
    const int M = in_sizes[1] / D;   // 8192

    const int smem_bytes = 2 * BM * PAD * sizeof(uint32_t)
                         + 2 * BM * sizeof(float);   // 69632 + 1024 = 70656
    cudaFuncSetAttribute(dist_kernel,
                         cudaFuncAttributeMaxDynamicSharedMemorySize, smem_bytes);

    norm_kernel<<<2 * NROWS / 256, 256>>>(x1, x2);

    dim3 grid(M / BN, N / BM);
    dist_kernel<<<grid, 128, smem_bytes>>>(x1, x2, out, M);
}